// round 9
// baseline (speedup 1.0000x reference)
#include <cuda_runtime.h>
#include <cuda_bf16.h>
#include <math.h>

#define B_ 8
#define C_ 64
#define H_ 128
#define W_ 128
#define HS 256
#define WS 256

__device__ __forceinline__ unsigned long long pack2(float lo, float hi)
{
    unsigned long long r;
    asm("mov.b64 %0, {%1, %2};" : "=l"(r) : "f"(lo), "f"(hi));
    return r;
}
__device__ __forceinline__ float2 unpack2(unsigned long long v)
{
    float lo, hi;
    asm("mov.b64 {%0, %1}, %2;" : "=f"(lo), "=f"(hi) : "l"(v));
    return make_float2(lo, hi);
}
#define FMA2(acc, ww, tt) \
    asm("fma.rn.f32x2 %0, %1, %2, %0;" : "+l"(acc) : "l"(ww), "l"(tt))

__device__ __forceinline__ float4 ldg4_or_zero(const float* p, bool pred)
{
    if (pred) return *(const float4*)p;
    return make_float4(0.f, 0.f, 0.f, 0.f);
}

// ---------------------------------------------------------------------------
// Single fused kernel, software-pipelined channel loop.
// Block = 128 thr = 4 warps = 2 low-res rows x 2 hi-res sub-rows.
// ---------------------------------------------------------------------------
__global__ void __launch_bounds__(128, 3) carafe_full_kernel(
    const float* __restrict__ x,
    const float* __restrict__ w_off,
    const float* __restrict__ b_off,
    float* __restrict__ out)
{
    __shared__ float sm[4][132];
    __shared__ float sc0[2][2][9];
    __shared__ float sc1[2][2][9];
    __shared__ float sbias[2];

    if (threadIdx.x < 4) {
        int ir = threadIdx.x >> 1, j = threadIdx.x & 1;
        float a0[9], a1[9];
#pragma unroll
        for (int k = 0; k < 9; k++) { a0[k] = 0.f; a1[k] = 0.f; }
#pragma unroll
        for (int pp = 0; pp < 5; pp++)
#pragma unroll
            for (int qq = 0; qq < 5; qq++) {
                int k = (((ir + pp - 2) >> 1) + 1) * 3 + (((j + qq - 2) >> 1) + 1);
                a0[k] += w_off[pp * 5 + qq];
                a1[k] += w_off[25 + pp * 5 + qq];
            }
#pragma unroll
        for (int k = 0; k < 9; k++) { sc0[ir][j][k] = a0[k]; sc1[ir][j][k] = a1[k]; }
    }
    if (threadIdx.x < 2) sbias[threadIdx.x] = b_off[threadIdx.x];

    int b  = blockIdx.x >> 6;
    int y0 = (blockIdx.x & 63) * 2;
    int warp = threadIdx.x >> 5;
    int lane = threadIdx.x & 31;

    // ---- Phase 1: mean of rows y0-1..y0+2, one row per warp, ILP-4 ----
    {
        int yy = y0 - 1 + warp;
        float4 a[4];
#pragma unroll
        for (int i = 0; i < 4; i++) a[i] = make_float4(0.f, 0.f, 0.f, 0.f);
        if (yy >= 0 && yy < H_) {
            const float4* px = (const float4*)(x + ((size_t)b << 20) + yy * W_) + lane;
#pragma unroll
            for (int c = 0; c < C_; c += 4) {
#pragma unroll
                for (int i = 0; i < 4; i++) {
                    float4 v = px[(size_t)(c + i) << 12];
                    a[i].x += v.x; a[i].y += v.y; a[i].z += v.z; a[i].w += v.w;
                }
            }
        }
        const float inv = 1.0f / 64.0f;
        sm[warp][1 + 4 * lane + 0] = (a[0].x + a[1].x + a[2].x + a[3].x) * inv;
        sm[warp][1 + 4 * lane + 1] = (a[0].y + a[1].y + a[2].y + a[3].y) * inv;
        sm[warp][1 + 4 * lane + 2] = (a[0].z + a[1].z + a[2].z + a[3].z) * inv;
        sm[warp][1 + 4 * lane + 3] = (a[0].w + a[1].w + a[2].w + a[3].w) * inv;
        if (lane == 0)  sm[warp][0]   = 0.f;
        if (lane == 31) sm[warp][129] = 0.f;
    }
    __syncthreads();

    // ---- Phase 2: per-thread weights (4 pixels x 2 subcols, one sub-row) ----
    int dy = warp & 1;
    int ir = warp >> 1;
    int y = y0 + dy;
    bool hasN = (y > 0), hasS = (y < H_ - 1);

    unsigned long long wp[4][9];       // [pp*2+j][k] = {w_pix2pp, w_pix2pp+1}
    {
        float mrow[3][6];
#pragma unroll
        for (int r = 0; r < 3; r++)
#pragma unroll
            for (int c = 0; c < 6; c++)
                mrow[r][c] = sm[dy + r][4 * lane + c];

        float lo[18];
#pragma unroll
        for (int p = 0; p < 4; p++) {
            float m0[9];
#pragma unroll
            for (int r = 0; r < 3; r++)
#pragma unroll
                for (int c = 0; c < 3; c++) m0[r * 3 + c] = mrow[r][p + c];
            float g9[9];
            float mc = m0[4];
#pragma unroll
            for (int k = 0; k < 9; k++) {
                float d = m0[k] - mc;
                g9[k] = __fdividef(1.0f, d * d + 1.0f);
            }
            float cur[18];
#pragma unroll
            for (int j = 0; j < 2; j++) {
                float o0 = 0.f, o1 = 0.f;
#pragma unroll
                for (int k = 0; k < 9; k++) {
                    o0 = fmaf(m0[k], sc0[ir][j][k], o0);
                    o1 = fmaf(m0[k], sc1[ir][j][k], o1);
                }
                float s0 = (ir ? 0.25f : -0.25f) + 0.25f * tanhf(o0 + sbias[0]);
                float s1 = (j  ? 0.25f : -0.25f) + 0.25f * tanhf(o1 + sbias[1]);
                float lv[9];
                float sum = 0.f;
#pragma unroll
                for (int k = 0; k < 9; k++) {
                    float d0 = s0 - (float)(k / 3 - 1);
                    float d1 = s1 - (float)(k % 3 - 1);
                    float ker = __fdividef(1.0f, d0 * d0 + d1 * d1 + 0.5f);
                    lv[k] = __expf(g9[k] * ker);
                    sum += lv[k];
                }
                float sinv = __fdividef(1.0f, sum);
#pragma unroll
                for (int k = 0; k < 9; k++) cur[j * 9 + k] = lv[k] * sinv;
            }
            if ((p & 1) == 0) {
#pragma unroll
                for (int t = 0; t < 18; t++) lo[t] = cur[t];
            } else {
#pragma unroll
                for (int j = 0; j < 2; j++)
#pragma unroll
                    for (int k = 0; k < 9; k++)
                        wp[(p >> 1) * 2 + j][k] = pack2(lo[j * 9 + k], cur[j * 9 + k]);
            }
        }
    }

    // ---- Phase 3: pipelined CARAFE channel loop ----
    const float* px = x + ((size_t)b << 20) + y * W_ + 4 * lane;
    float* ob = out + (size_t)b * C_ * (HS * WS)
                    + (size_t)(2 * y + ir) * WS + 8 * lane;

    const unsigned m = 0xffffffffu;
    bool z0 = (lane == 0), z31 = (lane == 31);

    // stage channel 0: loads + shuffles
    float4 q0 = ldg4_or_zero(px - W_, hasN);
    float4 q1 = *(const float4*)px;
    float4 q2 = ldg4_or_zero(px + W_, hasS);
    float lf0 = __shfl_up_sync(m, q0.w, 1);
    float lf1 = __shfl_up_sync(m, q1.w, 1);
    float lf2 = __shfl_up_sync(m, q2.w, 1);
    float rt0 = __shfl_down_sync(m, q0.x, 1);
    float rt1 = __shfl_down_sync(m, q1.x, 1);
    float rt2 = __shfl_down_sync(m, q2.x, 1);

#pragma unroll 1
    for (int c = 0; c < C_; c++) {
        // prefetch channel c+1 (warp-uniform guard; shuffles converged)
        float4 n0, n1, n2;
        float nlf0 = 0.f, nlf1 = 0.f, nlf2 = 0.f;
        float nrt0 = 0.f, nrt1 = 0.f, nrt2 = 0.f;
        if (c + 1 < C_) {
            const float* pn = px + 16384;
            n0 = ldg4_or_zero(pn - W_, hasN);
            n1 = *(const float4*)pn;
            n2 = ldg4_or_zero(pn + W_, hasS);
            nlf0 = __shfl_up_sync(m, n0.w, 1);
            nlf1 = __shfl_up_sync(m, n1.w, 1);
            nlf2 = __shfl_up_sync(m, n2.w, 1);
            nrt0 = __shfl_down_sync(m, n0.x, 1);
            nrt1 = __shfl_down_sync(m, n1.x, 1);
            nrt2 = __shfl_down_sync(m, n2.x, 1);
        } else {
            n0 = n1 = n2 = make_float4(0.f, 0.f, 0.f, 0.f);
        }

        // compute current channel
        float e0 = z0 ? 0.f : lf0, e1 = z0 ? 0.f : lf1, e2 = z0 ? 0.f : lf2;
        float f0 = z31 ? 0.f : rt0, f1 = z31 ? 0.f : rt1, f2 = z31 ? 0.f : rt2;

        unsigned long long tp[3][5];
        tp[0][0] = pack2(e0, q0.x); tp[0][1] = pack2(q0.x, q0.y);
        tp[0][2] = pack2(q0.y, q0.z); tp[0][3] = pack2(q0.z, q0.w);
        tp[0][4] = pack2(q0.w, f0);
        tp[1][0] = pack2(e1, q1.x); tp[1][1] = pack2(q1.x, q1.y);
        tp[1][2] = pack2(q1.y, q1.z); tp[1][3] = pack2(q1.z, q1.w);
        tp[1][4] = pack2(q1.w, f1);
        tp[2][0] = pack2(e2, q2.x); tp[2][1] = pack2(q2.x, q2.y);
        tp[2][2] = pack2(q2.y, q2.z); tp[2][3] = pack2(q2.z, q2.w);
        tp[2][4] = pack2(q2.w, f2);

        unsigned long long acc[2][2] = {{0ull, 0ull}, {0ull, 0ull}};
#pragma unroll
        for (int pp = 0; pp < 2; pp++)
#pragma unroll
            for (int r = 0; r < 3; r++)
#pragma unroll
                for (int cc = 0; cc < 3; cc++) {
                    int k = r * 3 + cc;
                    unsigned long long t = tp[r][2 * pp + cc];
                    FMA2(acc[pp][0], wp[pp * 2 + 0][k], t);
                    FMA2(acc[pp][1], wp[pp * 2 + 1][k], t);
                }

        float2 a00 = unpack2(acc[0][0]), a01 = unpack2(acc[0][1]);
        float2 a10 = unpack2(acc[1][0]), a11 = unpack2(acc[1][1]);

        __stcs((float4*)ob,       make_float4(a00.x, a01.x, a00.y, a01.y));
        __stcs((float4*)(ob + 4), make_float4(a10.x, a11.x, a10.y, a11.y));

        // rotate stages, advance pointers
        q0 = n0; q1 = n1; q2 = n2;
        lf0 = nlf0; lf1 = nlf1; lf2 = nlf2;
        rt0 = nrt0; rt1 = nrt1; rt2 = nrt2;
        px += 16384;
        ob += (size_t)HS * WS;
    }
}

extern "C" void kernel_launch(void* const* d_in, const int* in_sizes, int n_in,
                              void* d_out, int out_size)
{
    const float* x     = (const float*)d_in[0];   // [8,64,128,128]
    const float* w_off = (const float*)d_in[1];   // [2,1,5,5]
    const float* b_off = (const float*)d_in[2];   // [2]
    float* out = (float*)d_out;                   // [8,64,256,256]

    carafe_full_kernel<<<B_ * H_ / 2, 128>>>(x, w_off, b_off, out);
}